// round 4
// baseline (speedup 1.0000x reference)
#include <cuda_runtime.h>
#include <cuda_bf16.h>
#include <math.h>

// Problem constants (fixed-shape problem; runtime nrows still honored)
#define NQ      64
#define KDIM    768
#define TILE_N  128          // bank rows per block tile
#define CHUNK_K 64           // K chunk loaded per iteration
#define NCHUNK  (KDIM / CHUNK_K)   // 12
#define LDQ     776          // bf16 elems per q row in smem (768 + 8 pad, conflict-free A frags)
#define LDB     72           // bf16 elems per bank row chunk in smem (64 + 8 pad)
#define MAXROWS 500000
#define CAND    16           // screening candidates per query

// ---------------- device scratch (allocation-free rule: __device__ globals) ----
__device__ __align__(16) float          g_qn  [NQ * KDIM];        // exact fp32 normalized queries
__device__ __align__(16) __nv_bfloat16  g_qnb [NQ * KDIM];        // bf16 copy for MMA
__device__ __align__(16) float          g_sims[(size_t)NQ * MAXROWS];  // 128 MB sims
__device__                int           g_cand[NQ * CAND];        // screened candidate ids

// ---------------- kernel 1: normalize queries --------------------------------
__global__ void norm_q_kernel(const float* __restrict__ q) {
    __shared__ float red[256];
    int qi = blockIdx.x, tid = threadIdx.x;
    const float* qr = q + qi * KDIM;
    float v0 = qr[tid], v1 = qr[tid + 256], v2 = qr[tid + 512];
    red[tid] = v0 * v0 + v1 * v1 + v2 * v2;
    __syncthreads();
    for (int st = 128; st > 0; st >>= 1) {
        if (tid < st) red[tid] += red[tid + st];
        __syncthreads();
    }
    float inv = 1.0f / fmaxf(sqrtf(red[0]), 1e-12f);
    float o0 = v0 * inv, o1 = v1 * inv, o2 = v2 * inv;
    g_qn[qi * KDIM + tid      ] = o0;
    g_qn[qi * KDIM + tid + 256] = o1;
    g_qn[qi * KDIM + tid + 512] = o2;
    g_qnb[qi * KDIM + tid      ] = __float2bfloat16(o0);
    g_qnb[qi * KDIM + tid + 256] = __float2bfloat16(o1);
    g_qnb[qi * KDIM + tid + 512] = __float2bfloat16(o2);
}

// ---------------- kernel 2: bf16 MMA score, writes fp32 sims -----------------
// Block tile: 64 queries x 128 bank rows. 8 warps: warp = (qstrip[0..3], nstrip[0..1]),
// each warp owns a 16x64 output via mma.sync.m16n8k16 (bf16 in, f32 accum).
// Bank rows enter the MMA UN-normalized; fp32 1/||b|| applied in epilogue.
#define SCORE_SMEM (NQ * LDQ * 2 + TILE_N * LDB * 2 + TILE_N * 4)

__global__ __launch_bounds__(256, 1)
void score_kernel(const float* __restrict__ bank, int nrows) {
    extern __shared__ char smem[];
    __nv_bfloat16* qsm  = (__nv_bfloat16*)smem;                         // [NQ][LDQ]
    __nv_bfloat16* bsm  = (__nv_bfloat16*)(smem + NQ * LDQ * 2);        // [TILE_N][LDB]
    float*         invn = (float*)(smem + NQ * LDQ * 2 + TILE_N * LDB * 2); // [TILE_N]

    const int tid = threadIdx.x;

    // stage all 64 normalized bf16 queries into smem (L2-resident source, ~98 KB)
    {
        const unsigned int* qg = (const unsigned int*)g_qnb;
        for (int i = tid; i < NQ * KDIM / 2; i += 256) {
            int qi = i / (KDIM / 2);
            int k2 = i % (KDIM / 2);
            *(unsigned int*)&qsm[qi * LDQ + 2 * k2] = qg[i];
        }
    }

    const int tile_base = blockIdx.x * TILE_N;
    const int r = tid >> 1;        // 0..127: smem bank row
    const int h = tid & 1;         // column half (32 floats)
    const long long grow = (long long)tile_base + r;
    const bool valid = (grow < (long long)nrows);
    const float* brow = bank + grow * KDIM + h * 32;
    float ssq = 0.f;

    const int lane = tid & 31, warp = tid >> 5;
    const int qbase = (warp >> 1) * 16;
    const int nbase = (warp & 1) * 64;
    const int l4 = lane >> 2, lm4 = lane & 3;

    float acc[8][4];
    #pragma unroll
    for (int i = 0; i < 8; i++)
        #pragma unroll
        for (int j = 0; j < 4; j++) acc[i][j] = 0.f;

    for (int c = 0; c < NCHUNK; c++) {
        // load chunk: this thread owns 32 floats of one bank row, fixed slot every chunk
        if (valid) {
            #pragma unroll
            for (int j = 0; j < 8; j++) {
                float4 f = *(const float4*)(brow + c * CHUNK_K + j * 4);
                ssq += f.x * f.x + f.y * f.y + f.z * f.z + f.w * f.w;
                __nv_bfloat162 p0 = __floats2bfloat162_rn(f.x, f.y);
                __nv_bfloat162 p1 = __floats2bfloat162_rn(f.z, f.w);
                uint2 u;
                u.x = *(unsigned int*)&p0;
                u.y = *(unsigned int*)&p1;
                *(uint2*)&bsm[r * LDB + h * 32 + j * 4] = u;
            }
        } else if (c == 0) {
            // zero once; slot is reused identically each chunk, so zeros persist
            #pragma unroll
            for (int j = 0; j < 8; j++)
                *(uint2*)&bsm[r * LDB + h * 32 + j * 4] = make_uint2(0u, 0u);
        }
        __syncthreads();

        const int kg = c * CHUNK_K;
        #pragma unroll
        for (int kk = 0; kk < CHUNK_K / 16; kk++) {
            const int k0 = kk * 16;
            // A fragments (16x16 bf16, row-major, K contiguous)
            unsigned int a0 = *(const unsigned int*)&qsm[(qbase + l4    ) * LDQ + kg + k0 +     lm4 * 2];
            unsigned int a1 = *(const unsigned int*)&qsm[(qbase + l4 + 8) * LDQ + kg + k0 +     lm4 * 2];
            unsigned int a2 = *(const unsigned int*)&qsm[(qbase + l4    ) * LDQ + kg + k0 + 8 + lm4 * 2];
            unsigned int a3 = *(const unsigned int*)&qsm[(qbase + l4 + 8) * LDQ + kg + k0 + 8 + lm4 * 2];
            #pragma unroll
            for (int nt = 0; nt < 8; nt++) {
                const int nr = nbase + nt * 8 + l4;
                unsigned int b0 = *(const unsigned int*)&bsm[nr * LDB + k0 +     lm4 * 2];
                unsigned int b1 = *(const unsigned int*)&bsm[nr * LDB + k0 + 8 + lm4 * 2];
                asm volatile(
                    "mma.sync.aligned.m16n8k16.row.col.f32.bf16.bf16.f32 "
                    "{%0,%1,%2,%3}, {%4,%5,%6,%7}, {%8,%9}, {%0,%1,%2,%3};\n"
                    : "+f"(acc[nt][0]), "+f"(acc[nt][1]), "+f"(acc[nt][2]), "+f"(acc[nt][3])
                    : "r"(a0), "r"(a1), "r"(a2), "r"(a3), "r"(b0), "r"(b1));
            }
        }
        __syncthreads();
    }

    // row inverse norms: combine the two column-halves (lanes tid and tid^1 adjacent)
    float other = __shfl_xor_sync(0xffffffffu, ssq, 1);
    if (h == 0) {
        float tot = ssq + other;
        invn[r] = 1.0f / fmaxf(sqrtf(tot), 1e-12f);
    }
    __syncthreads();

    // epilogue: sims[q][row] = acc * invnorm(row)
    #pragma unroll
    for (int nt = 0; nt < 8; nt++) {
        const int n0  = nbase + nt * 8 + lm4 * 2;     // even
        const int gr0 = tile_base + n0;
        if (gr0 < nrows) {                            // gr0 even, nrows even -> gr0+1 valid too
            const float i0 = invn[n0], i1 = invn[n0 + 1];
            const int q0 = qbase + l4;
            float2 v;
            v.x = acc[nt][0] * i0; v.y = acc[nt][1] * i1;
            *(float2*)&g_sims[(long long)q0 * nrows + gr0] = v;
            v.x = acc[nt][2] * i0; v.y = acc[nt][3] * i1;
            *(float2*)&g_sims[(long long)(q0 + 8) * nrows + gr0] = v;
        }
    }
}

// ---------------- kernel 3: per-query top-16 screening -----------------------
#define TOPK_THREADS 1024
#define TOPK_SMEM    (TOPK_THREADS * CAND * 8)

__device__ __forceinline__ void topk_insert(float (&v)[CAND], int (&id)[CAND],
                                            float nv, int ni) {
    if (nv <= v[CAND - 1]) return;
    int j = CAND - 1;
    while (j > 0 && nv > v[j - 1]) {
        v[j] = v[j - 1]; id[j] = id[j - 1]; j--;
    }
    v[j] = nv; id[j] = ni;
}

__global__ __launch_bounds__(TOPK_THREADS, 1)
void topk_kernel(int nrows) {
    extern __shared__ char sm[];
    float* sv = (float*)sm;                                // [threads][CAND]
    int*   si = (int*)(sm + TOPK_THREADS * CAND * 4);      // [threads][CAND]

    const int q = blockIdx.x, tid = threadIdx.x;
    const float* s = g_sims + (long long)q * nrows;

    float vals[CAND]; int ids[CAND];
    #pragma unroll
    for (int i = 0; i < CAND; i++) { vals[i] = -3e38f; ids[i] = 0; }

    const int n4 = nrows >> 2;
    const float4* s4 = (const float4*)s;
    for (int i = tid; i < n4; i += TOPK_THREADS) {
        float4 f = s4[i];
        int base = i << 2;
        topk_insert(vals, ids, f.x, base);
        topk_insert(vals, ids, f.y, base + 1);
        topk_insert(vals, ids, f.z, base + 2);
        topk_insert(vals, ids, f.w, base + 3);
    }
    for (int i = (n4 << 2) + tid; i < nrows; i += TOPK_THREADS)
        topk_insert(vals, ids, s[i], i);

    #pragma unroll
    for (int i = 0; i < CAND; i++) { sv[tid * CAND + i] = vals[i]; si[tid * CAND + i] = ids[i]; }
    __syncthreads();

    // tree merge of sorted-16 lists
    for (int st = TOPK_THREADS / 2; st > 0; st >>= 1) {
        if (tid < st) {
            const int ao = tid * CAND, bo = (tid + st) * CAND;
            float ov[CAND]; int oi[CAND];
            int ia = 0, ib = 0;
            #pragma unroll
            for (int o = 0; o < CAND; o++) {
                float va = (ia < CAND) ? sv[ao + ia] : -3.4e38f;
                float vb = (ib < CAND) ? sv[bo + ib] : -3.4e38f;
                bool takeA;
                if (va > vb) takeA = true;
                else if (va < vb) takeA = false;
                else takeA = (si[ao + ia] <= si[bo + ib]);
                if (takeA) { ov[o] = va; oi[o] = si[ao + ia]; ia++; }
                else       { ov[o] = vb; oi[o] = si[bo + ib]; ib++; }
            }
            #pragma unroll
            for (int o = 0; o < CAND; o++) { sv[ao + o] = ov[o]; si[ao + o] = oi[o]; }
        }
        __syncthreads();
    }

    if (tid == 0) {
        #pragma unroll
        for (int i = 0; i < CAND; i++) g_cand[q * CAND + i] = si[i];
    }
}

// ---------------- kernel 4: exact fp32 rescore + final top-k -----------------
__global__ void final_kernel(const float* __restrict__ bank, float* __restrict__ out,
                             int nrows, int k) {
    __shared__ float sv[CAND];
    __shared__ int   sid[CAND];
    const int q = blockIdx.x, tid = threadIdx.x;
    const int lane = tid & 31, warp = tid >> 5;

    for (int c = warp; c < CAND; c += 8) {
        const int id = g_cand[q * CAND + c];
        const float* b  = bank + (long long)id * KDIM;
        const float* qv = g_qn + q * KDIM;
        float dot = 0.f, ss = 0.f;
        for (int j = lane; j < KDIM; j += 32) {
            float bv = b[j];
            dot = fmaf(qv[j], bv, dot);
            ss  = fmaf(bv, bv, ss);
        }
        #pragma unroll
        for (int o = 16; o; o >>= 1) {
            dot += __shfl_xor_sync(0xffffffffu, dot, o);
            ss  += __shfl_xor_sync(0xffffffffu, ss,  o);
        }
        if (lane == 0) {
            sv[c]  = dot / fmaxf(sqrtf(ss), 1e-12f);
            sid[c] = id;
        }
    }
    __syncthreads();

    if (tid == 0) {
        bool used[CAND];
        #pragma unroll
        for (int i = 0; i < CAND; i++) used[i] = false;
        for (int j = 0; j < k; j++) {
            int best = -1; float bv = -3.4e38f;
            for (int i = 0; i < CAND; i++) {
                if (used[i]) continue;
                if (sv[i] > bv || (best >= 0 && sv[i] == bv && sid[i] < sid[best])) {
                    bv = sv[i]; best = i;
                }
            }
            used[best] = true;
            out[q * k + j]            = bv;               // values block
            out[NQ * k + q * k + j]   = (float)sid[best]; // indices block (as float)
        }
    }
}

// ---------------- launch -----------------------------------------------------
extern "C" void kernel_launch(void* const* d_in, const int* in_sizes, int n_in,
                              void* d_out, int out_size) {
    const float* query = (const float*)d_in[0];
    const float* bank  = (const float*)d_in[1];
    const int nrows = in_sizes[1] / KDIM;
    const int k = out_size / (2 * NQ);   // out = [vals(64*k) ; ids(64*k)] as float32

    cudaFuncSetAttribute(score_kernel, cudaFuncAttributeMaxDynamicSharedMemorySize, SCORE_SMEM);
    cudaFuncSetAttribute(topk_kernel,  cudaFuncAttributeMaxDynamicSharedMemorySize, TOPK_SMEM);

    norm_q_kernel<<<NQ, 256>>>(query);

    const int ntiles = (nrows + TILE_N - 1) / TILE_N;
    score_kernel<<<ntiles, 256, SCORE_SMEM>>>(bank, nrows);

    topk_kernel<<<NQ, TOPK_THREADS, TOPK_SMEM>>>(nrows);

    final_kernel<<<NQ, 256>>>(bank, (float*)d_out, nrows, k);
}

// round 8
// speedup vs baseline: 1.5190x; 1.5190x over previous
#include <cuda_runtime.h>
#include <cuda_bf16.h>
#include <math.h>

// ---------------- problem constants ------------------------------------------
#define NQ      64
#define KDIM    768
#define TILE_M  128                 // bank rows per CTA tile
#define CHUNK_K 64                  // K elems per chunk (bf16 row = 128 B)
#define NCHUNK  (KDIM / CHUNK_K)    // 12
#define MAXROWS 500000
#define NSEG    8                   // top-k segments per query
#define SEGK    16                  // candidates kept per (q, segment)
#define CAND    16                  // candidates exactly rescored per query
#define TB_PAD  136                 // transpose buffer row pitch (bf16 elems)

// ---------------- smem layout (score kernel) ---------------------------------
#define SM_INVN 0                                   // float[128]
#define SM_Q    1024                                // 12 chunks x 64 q x 128 B
#define SM_BB   (SM_Q + NCHUNK * 64 * 128)          // 99328: B buf (16 KB) / transpose buf
#define SCORE_SMEM (SM_BB + NQ * TB_PAD * 2)        // 99328 + 17408 = 116736

// ---------------- device scratch (allocation-free rule) ----------------------
__device__ __align__(16) float         g_qn   [NQ * KDIM];            // fp32 normalized queries
__device__ __align__(16) __nv_bfloat16 g_qnb  [NQ * KDIM];            // bf16 copy
__device__ __align__(16) __nv_bfloat16 g_simsb[(size_t)NQ * MAXROWS]; // 64 MB bf16 sims
__device__ float g_segv[NQ * NSEG * SEGK];
__device__ int   g_segi[NQ * NSEG * SEGK];

// ---------------- kernel 1: normalize queries --------------------------------
__global__ void norm_q_kernel(const float* __restrict__ q) {
    __shared__ float red[256];
    int qi = blockIdx.x, tid = threadIdx.x;
    const float* qr = q + qi * KDIM;
    float v0 = qr[tid], v1 = qr[tid + 256], v2 = qr[tid + 512];
    red[tid] = v0 * v0 + v1 * v1 + v2 * v2;
    __syncthreads();
    for (int st = 128; st > 0; st >>= 1) {
        if (tid < st) red[tid] += red[tid + st];
        __syncthreads();
    }
    float inv = 1.0f / fmaxf(sqrtf(red[0]), 1e-12f);
    float o0 = v0 * inv, o1 = v1 * inv, o2 = v2 * inv;
    g_qn[qi * KDIM + tid      ] = o0;
    g_qn[qi * KDIM + tid + 256] = o1;
    g_qn[qi * KDIM + tid + 512] = o2;
    g_qnb[qi * KDIM + tid      ] = __float2bfloat16(o0);
    g_qnb[qi * KDIM + tid + 256] = __float2bfloat16(o1);
    g_qnb[qi * KDIM + tid + 512] = __float2bfloat16(o2);
}

// ---------------- kernel 2: mma.sync score -----------------------------------
// Load mapping: 16 lanes cover one 256-B fp32 chunk-row -> warp LDG.128s are
// line-contiguous (nL=4). Thread owns 8 (row, 16B) slots: row = p*16+warp*2+lr.
__device__ __forceinline__ void ld_chunk(float4 (&f)[8], const float* const (&rp)[8],
                                         const bool (&vld)[8], int c) {
    #pragma unroll
    for (int p = 0; p < 8; p++) {
        if (vld[p]) f[p] = *(const float4*)(rp[p] + c * CHUNK_K);
        else        f[p] = make_float4(0.f, 0.f, 0.f, 0.f);
    }
}

__device__ __forceinline__ void ldsm_x4(unsigned& r0, unsigned& r1, unsigned& r2,
                                        unsigned& r3, unsigned addr) {
    asm volatile("ldmatrix.sync.aligned.m8n8.x4.shared.b16 {%0,%1,%2,%3}, [%4];"
                 : "=r"(r0), "=r"(r1), "=r"(r2), "=r"(r3) : "r"(addr));
}

__device__ __forceinline__ unsigned s2u(const void* p) {
    unsigned a;
    asm("{ .reg .u64 t; cvta.to.shared.u64 t, %1; cvt.u32.u64 %0, t; }" : "=r"(a) : "l"(p));
    return a;
}

__global__ __launch_bounds__(256, 1)
void score_kernel(const float* __restrict__ bank, int nrows) {
    extern __shared__ char smem[];
    const unsigned sbase = s2u(smem);
    const int tid = threadIdx.x, warp = tid >> 5, lane = tid & 31;
    const int lr = lane >> 4, lc = lane & 15;

    // ---- global load mapping --------------------------------------------------
    int rloc[8]; const float* rp[8]; bool vld[8]; float ssq[8];
    #pragma unroll
    for (int p = 0; p < 8; p++) {
        int r = p * 16 + warp * 2 + lr;
        rloc[p] = r;
        long long grow = (long long)blockIdx.x * TILE_M + r;
        vld[p] = grow < (long long)nrows;
        rp[p]  = bank + grow * (long long)KDIM + lc * 4;
        ssq[p] = 0.f;
    }
    const int scol = (lc * 8) ^ (((warp * 2 + lr) & 7) << 4);  // row&7 is p-invariant

    // ---- stage all queries: [chunk][64 q][128 B], XOR-swizzled ----------------
    for (int i = tid; i < NQ * KDIM / 4; i += 256) {
        int qi  = i / 192;
        int rem = i - qi * 192;
        int c   = rem >> 4;
        int k4  = rem & 15;
        uint2 v = ((const uint2*)g_qnb)[i];
        *(uint2*)(smem + SM_Q + c * 8192 + qi * 128 + ((k4 * 8) ^ ((qi & 7) << 4))) = v;
    }

    // ---- mma thread constants -------------------------------------------------
    const int qbase = (warp & 3) * 16;          // m (query) strip
    const int nbase = (warp >> 2) * 64;         // n (bank row) strip
    const int arow  = qbase + ((lane >> 3) & 1) * 8 + (lane & 7);
    const int axtr  = (lane >> 4) * 16;
    const int brow0 = nbase + ((lane >> 4) & 1) * 8 + (lane & 7);   // + pair*16
    const int bxtr  = ((lane >> 3) & 1) * 16;
    const int lsw   = (lane & 7) << 4;          // swizzle term (row&7 == lane&7)

    float acc[8][4];
    #pragma unroll
    for (int i = 0; i < 8; i++)
        #pragma unroll
        for (int j = 0; j < 4; j++) acc[i][j] = 0.f;

    float4 f[8];
    ld_chunk(f, rp, vld, 0);           // prologue: chunk 0 in flight

    for (int c = 0; c < NCHUNK; c++) {
        // convert + STS chunk c (waits on its LDGs via register scoreboard)
        #pragma unroll
        for (int p = 0; p < 8; p++) {
            float4 fv = f[p];
            ssq[p] += fv.x * fv.x + fv.y * fv.y + fv.z * fv.z + fv.w * fv.w;
            __nv_bfloat162 p0 = __floats2bfloat162_rn(fv.x, fv.y);
            __nv_bfloat162 p1 = __floats2bfloat162_rn(fv.z, fv.w);
            uint2 u;
            u.x = *(unsigned*)&p0;
            u.y = *(unsigned*)&p1;
            *(uint2*)(smem + SM_BB + rloc[p] * 128 + scol) = u;
        }
        __syncthreads();

        // issue next chunk's loads BEFORE mma work (latency hidden behind mma)
        if (c + 1 < NCHUNK) ld_chunk(f, rp, vld, c + 1);

        // mma over chunk c: 4 k16 steps x 8 ntiles
        const unsigned qb = sbase + SM_Q + c * 8192;
        const unsigned bb = sbase + SM_BB;
        #pragma unroll
        for (int kk = 0; kk < 4; kk++) {
            unsigned a0, a1, a2, a3;
            ldsm_x4(a0, a1, a2, a3,
                    qb + arow * 128 + ((kk * 32 + axtr) ^ lsw));
            #pragma unroll
            for (int pair = 0; pair < 4; pair++) {
                unsigned b0, b1, b2, b3;
                ldsm_x4(b0, b1, b2, b3,
                        bb + (brow0 + pair * 16) * 128 + ((kk * 32 + bxtr) ^ lsw));
                asm volatile(
                    "mma.sync.aligned.m16n8k16.row.col.f32.bf16.bf16.f32 "
                    "{%0,%1,%2,%3}, {%4,%5,%6,%7}, {%8,%9}, {%0,%1,%2,%3};\n"
                    : "+f"(acc[pair*2][0]), "+f"(acc[pair*2][1]),
                      "+f"(acc[pair*2][2]), "+f"(acc[pair*2][3])
                    : "r"(a0), "r"(a1), "r"(a2), "r"(a3), "r"(b0), "r"(b1));
                asm volatile(
                    "mma.sync.aligned.m16n8k16.row.col.f32.bf16.bf16.f32 "
                    "{%0,%1,%2,%3}, {%4,%5,%6,%7}, {%8,%9}, {%0,%1,%2,%3};\n"
                    : "+f"(acc[pair*2+1][0]), "+f"(acc[pair*2+1][1]),
                      "+f"(acc[pair*2+1][2]), "+f"(acc[pair*2+1][3])
                    : "r"(a0), "r"(a1), "r"(a2), "r"(a3), "r"(b2), "r"(b3));
            }
        }
        __syncthreads();
    }

    // ---- row inverse norms (16 lanes share a row) -----------------------------
    float* invn = (float*)(smem + SM_INVN);
    #pragma unroll
    for (int p = 0; p < 8; p++) {
        float s = ssq[p];
        s += __shfl_xor_sync(0xffffffffu, s, 1);
        s += __shfl_xor_sync(0xffffffffu, s, 2);
        s += __shfl_xor_sync(0xffffffffu, s, 4);
        s += __shfl_xor_sync(0xffffffffu, s, 8);
        if (lc == 0) invn[rloc[p]] = 1.0f / fmaxf(sqrtf(s), 1e-12f);
    }
    __syncthreads();

    // ---- epilogue 1: regs -> smem transpose buffer [q][TB_PAD] bf16 -----------
    {
        __nv_bfloat16* tb = (__nv_bfloat16*)(smem + SM_BB);
        const int q0 = qbase + (lane >> 2);
        #pragma unroll
        for (int nt = 0; nt < 8; nt++) {
            const int r0 = nbase + nt * 8 + (lane & 3) * 2;
            const float i0 = invn[r0], i1 = invn[r0 + 1];
            __nv_bfloat162 v01 = __floats2bfloat162_rn(acc[nt][0] * i0, acc[nt][1] * i1);
            __nv_bfloat162 v23 = __floats2bfloat162_rn(acc[nt][2] * i0, acc[nt][3] * i1);
            *(__nv_bfloat162*)&tb[ q0      * TB_PAD + r0] = v01;
            *(__nv_bfloat162*)&tb[(q0 + 8) * TB_PAD + r0] = v23;
        }
    }
    __syncthreads();

    // ---- epilogue 2: coalesced vectorized sims store --------------------------
    {
        const int q = tid >> 2, seg = tid & 3;
        const long long tb0 = (long long)blockIdx.x * TILE_M;
        const __nv_bfloat16* tb = (const __nv_bfloat16*)(smem + SM_BB);
        __nv_bfloat16* dst = g_simsb + (size_t)q * nrows;
        if ((nrows & 7) == 0) {
            #pragma unroll
            for (int i = 0; i < 4; i++) {
                long long g0 = tb0 + seg * 32 + i * 8;
                if (g0 + 8 <= (long long)nrows) {
                    uint4 v = *(const uint4*)(smem + SM_BB + q * (TB_PAD * 2) + seg * 64 + i * 16);
                    *(uint4*)(dst + g0) = v;
                } else {
                    for (int e = 0; e < 8 && g0 + e < (long long)nrows; e++)
                        dst[g0 + e] = tb[q * TB_PAD + seg * 32 + i * 8 + e];
                }
            }
        } else {
            for (int i = 0; i < 32; i++) {
                long long g0 = tb0 + seg * 32 + i;
                if (g0 < (long long)nrows) dst[g0] = tb[q * TB_PAD + seg * 32 + i];
            }
        }
    }
}

// ---------------- kernel 3: segmented top-16 screening -----------------------
__device__ __forceinline__ void tk_insert(float (&v)[SEGK], int (&id)[SEGK],
                                          float nv, int ni) {
    if (nv <= v[SEGK - 1]) return;
    int j = SEGK - 1;
    while (j > 0 && nv > v[j - 1]) { v[j] = v[j - 1]; id[j] = id[j - 1]; j--; }
    v[j] = nv; id[j] = ni;
}

__global__ __launch_bounds__(256, 1) void topk_kernel(int nrows) {
    __shared__ float sv[256 * SEGK];
    __shared__ int   si[256 * SEGK];
    const int seg = blockIdx.x, q = blockIdx.y, tid = threadIdx.x;
    const int len  = ((nrows + NSEG - 1) / NSEG + 3) & ~3;
    const int base = seg * len;
    const int end  = min(base + len, nrows);
    const __nv_bfloat16* s = g_simsb + (size_t)q * nrows;

    float vals[SEGK]; int ids[SEGK];
    #pragma unroll
    for (int i = 0; i < SEGK; i++) { vals[i] = -3.4e38f; ids[i] = 0x7fffffff; }

    if ((nrows & 3) == 0 && base < end) {
        const uint2* s4 = (const uint2*)s;
        for (int i = (base >> 2) + tid; i < (end >> 2); i += 256) {
            uint2 u = s4[i];
            __nv_bfloat162 p0 = *(__nv_bfloat162*)&u.x;
            __nv_bfloat162 p1 = *(__nv_bfloat162*)&u.y;
            int bi = i << 2;
            tk_insert(vals, ids, __low2float(p0),  bi);
            tk_insert(vals, ids, __high2float(p0), bi + 1);
            tk_insert(vals, ids, __low2float(p1),  bi + 2);
            tk_insert(vals, ids, __high2float(p1), bi + 3);
        }
    } else {
        for (int i = base + tid; i < end; i += 256)
            tk_insert(vals, ids, __bfloat162float(s[i]), i);
    }

    #pragma unroll
    for (int i = 0; i < SEGK; i++) { sv[tid * SEGK + i] = vals[i]; si[tid * SEGK + i] = ids[i]; }
    __syncthreads();

    // tree merge of sorted-16 lists (bounded reads, R4-verified pattern)
    for (int st = 128; st > 0; st >>= 1) {
        if (tid < st) {
            const int ao = tid * SEGK, bo = (tid + st) * SEGK;
            float ov[SEGK]; int oi[SEGK];
            int ia = 0, ib = 0;
            #pragma unroll
            for (int o = 0; o < SEGK; o++) {
                float va = (ia < SEGK) ? sv[ao + ia] : -3.4e38f;
                float vb = (ib < SEGK) ? sv[bo + ib] : -3.4e38f;
                bool takeA;
                if (va > vb) takeA = true;
                else if (va < vb) takeA = false;
                else takeA = (si[ao + min(ia, SEGK - 1)] <= si[bo + min(ib, SEGK - 1)]);
                if (takeA) { ov[o] = va; oi[o] = si[ao + min(ia, SEGK - 1)]; ia++; }
                else       { ov[o] = vb; oi[o] = si[bo + min(ib, SEGK - 1)]; ib++; }
            }
            #pragma unroll
            for (int o = 0; o < SEGK; o++) { sv[ao + o] = ov[o]; si[ao + o] = oi[o]; }
        }
        __syncthreads();
    }

    if (tid == 0) {
        #pragma unroll
        for (int i = 0; i < SEGK; i++) {
            g_segv[(q * NSEG + seg) * SEGK + i] = sv[i];
            g_segi[(q * NSEG + seg) * SEGK + i] = si[i];
        }
    }
}

// ---------------- kernel 4: merge + exact fp32 rescore + final top-k ---------
__global__ void final_kernel(const float* __restrict__ bank, float* __restrict__ out,
                             int nrows, int k) {
    __shared__ float cv[NSEG * SEGK];
    __shared__ int   ci[NSEG * SEGK];
    __shared__ float sv[CAND];
    __shared__ int   sid[CAND];
    __shared__ float rv[CAND];
    const int q = blockIdx.x, tid = threadIdx.x;
    const int lane = tid & 31, warp = tid >> 5;

    if (tid < NSEG * SEGK) {
        cv[tid] = g_segv[q * NSEG * SEGK + tid];
        ci[tid] = g_segi[q * NSEG * SEGK + tid];
    }
    __syncthreads();

    if (tid == 0) {
        float bv[CAND]; int bi[CAND];
        #pragma unroll
        for (int i = 0; i < CAND; i++) { bv[i] = -3.4e38f; bi[i] = 0x7fffffff; }
        for (int i = 0; i < NSEG * SEGK; i++) {
            float v = cv[i]; int id = ci[i];
            float lv = bv[CAND - 1]; int li = bi[CAND - 1];
            if (v < lv || (v == lv && id >= li)) continue;
            int j = CAND - 1;
            while (j > 0 && (v > bv[j - 1] || (v == bv[j - 1] && id < bi[j - 1]))) {
                bv[j] = bv[j - 1]; bi[j] = bi[j - 1]; j--;
            }
            bv[j] = v; bi[j] = id;
        }
        #pragma unroll
        for (int i = 0; i < CAND; i++) { sv[i] = bv[i]; sid[i] = bi[i]; }
    }
    __syncthreads();

    for (int c = warp; c < CAND; c += 8) {
        const int id = sid[c];
        float val = -3.4e38f;
        if (id < nrows) {
            const float* b  = bank + (long long)id * KDIM;
            const float* qv = g_qn + q * KDIM;
            float dot = 0.f, ss = 0.f;
            for (int j = lane; j < KDIM; j += 32) {
                float bvv = b[j];
                dot = fmaf(qv[j], bvv, dot);
                ss  = fmaf(bvv, bvv, ss);
            }
            #pragma unroll
            for (int o = 16; o; o >>= 1) {
                dot += __shfl_xor_sync(0xffffffffu, dot, o);
                ss  += __shfl_xor_sync(0xffffffffu, ss,  o);
            }
            val = dot / fmaxf(sqrtf(ss), 1e-12f);
        }
        if (lane == 0) rv[c] = val;
    }
    __syncthreads();

    if (tid == 0) {
        bool used[CAND];
        #pragma unroll
        for (int i = 0; i < CAND; i++) used[i] = false;
        for (int j = 0; j < k; j++) {
            int best = -1; float bvv = -3.4e38f;
            for (int i = 0; i < CAND; i++) {
                if (used[i]) continue;
                if (best < 0 || rv[i] > bvv ||
                    (rv[i] == bvv && sid[i] < sid[best])) { bvv = rv[i]; best = i; }
            }
            used[best] = true;
            out[q * k + j]          = bvv;
            out[NQ * k + q * k + j] = (float)sid[best];
        }
    }
}

// ---------------- launch -----------------------------------------------------
extern "C" void kernel_launch(void* const* d_in, const int* in_sizes, int n_in,
                              void* d_out, int out_size) {
    const float* query = (const float*)d_in[0];
    const float* bank  = (const float*)d_in[1];
    const int nrows = in_sizes[1] / KDIM;
    const int k = out_size / (2 * NQ);

    cudaFuncSetAttribute(score_kernel, cudaFuncAttributeMaxDynamicSharedMemorySize, SCORE_SMEM);

    norm_q_kernel<<<NQ, 256>>>(query);

    const int ntiles = (nrows + TILE_M - 1) / TILE_M;
    score_kernel<<<ntiles, 256, SCORE_SMEM>>>(bank, nrows);

    topk_kernel<<<dim3(NSEG, NQ), 256>>>(nrows);

    final_kernel<<<NQ, 256>>>(bank, (float*)d_out, nrows, k);
}